// round 15
// baseline (speedup 1.0000x reference)
#include <cuda_runtime.h>
#include <cuda_bf16.h>
#include <cstdint>

#define HDIM 128
#define PDIM 18
#define RDIM 18
#define NNODES 50000
#define NB2 (NNODES * RDIM)      // 900000 (dst*18 + r) buckets
#define NTILES 391
#define NROWS (NTILES * 128)     // 50048
#define MAXE 800000
#define PSTRIDE 32               // eproba row stride (f32)
#define KUF 352                  // K padded (bf16 elems per row)
#define KU32 176                 // u32 (bf16x2) per row
#define NCH 11                   // k chunks of 32 bf16 (16 u32)
#define SMS 20                   // pipeline smem row stride in u32
#define CTS 129                  // epilogue C-tile stride (f32)
#define PS_OFF 16512             // f32 offset of protos in gemm smem (128*129)
#define LMAX 3

// ---------------- scratch (device globals; no allocations allowed) ----------------
__device__ float         g_hidden[NNODES * HDIM];     // last-layer output only
__device__ float         g_eproba[NNODES * PSTRIDE];  // [n][p]=exl*proba, [n][31]=exl
__device__ float         g_rden[NNODES];
__device__ __nv_bfloat16 g_A[(size_t)NROWS * KUF];
__device__ __nv_bfloat16 g_B[LMAX * 128 * KUF];
__device__ int           g_cnt[NNODES];               // node hist; zeroed by scanall
__device__ int           g_cnt2[NB2];                 // bucket hist; zeroed by off2
__device__ int           g_run2[NB2];                 // rank counters; zeroed by off2
__device__ int           g_off[NNODES + 1];
__device__ int           g_off2[NB2 + 1];
__device__ int           g_srcs[MAXE];                // packed (src<<5)|r, (dst,r)-sorted

// ---------------- helpers ----------------
__device__ __forceinline__ void cp_async16(void* sdst, const void* gsrc) {
    unsigned s = (unsigned)__cvta_generic_to_shared(sdst);
    asm volatile("cp.async.cg.shared.global [%0], [%1], 16;\n" :: "r"(s), "l"(gsrc));
}
#define CP_COMMIT() asm volatile("cp.async.commit_group;\n" ::: "memory")
#define CP_WAIT(n)  asm volatile("cp.async.wait_group %0;\n" :: "n"(n) : "memory")

__device__ __forceinline__ void mma_bf16(float* c, const unsigned* a, const unsigned* b) {
    asm volatile(
        "mma.sync.aligned.m16n8k16.row.col.f32.bf16.bf16.f32 "
        "{%0,%1,%2,%3}, {%4,%5,%6,%7}, {%8,%9}, {%0,%1,%2,%3};\n"
        : "+f"(c[0]), "+f"(c[1]), "+f"(c[2]), "+f"(c[3])
        : "r"(a[0]), "r"(a[1]), "r"(a[2]), "r"(a[3]), "r"(b[0]), "r"(b[1]));
}

// normalize PDIM proto rows into smem ps[]
__device__ __forceinline__ void proto_to_smem(const float* __restrict__ proto, float* ps) {
    int warp = threadIdx.x >> 5, lane = threadIdx.x & 31;
    int nw = blockDim.x >> 5;
    for (int p = warp; p < PDIM; p += nw) {
        float4 v = ((const float4*)(proto + p * HDIM))[lane];
        float ss = v.x * v.x + v.y * v.y + v.z * v.z + v.w * v.w;
        #pragma unroll
        for (int o = 16; o; o >>= 1) ss += __shfl_xor_sync(0xffffffffu, ss, o);
        float inv = 1.f / fmaxf(sqrtf(ss), 1e-12f);
        ((float4*)(ps + p * HDIM))[lane] = make_float4(v.x * inv, v.y * inv, v.z * inv, v.w * inv);
    }
    __syncthreads();
}

// ---------------- setup (cnt/cnt2 assumed zero): both hists + A pad + B build ----------------
__global__ void k_setup(const int* __restrict__ dst, const int* __restrict__ et,
                        int* __restrict__ cnt, int* __restrict__ cnt2, int E,
                        __nv_bfloat16* __restrict__ A,
                        const float* __restrict__ M, __nv_bfloat16* __restrict__ B,
                        int btotal) {
    int i = blockIdx.x * blockDim.x + threadIdx.x;
    if (i < E) {
        int d = dst[i];
        atomicAdd(&cnt[d], 1);
        atomicAdd(&cnt2[d * RDIM + et[i]], 1);
    }
    if (i < (NROWS - NNODES) * KUF)
        A[(size_t)NNODES * KUF + i] = __float2bfloat16(0.f);
    if (i < btotal) {                          // B[l][h][k] = bf16(M[l][k/18][k%18][h])
        int l = i / (128 * KUF);
        int rem = i - l * 128 * KUF;
        int h = rem / KUF, k = rem % KUF;
        float v = 0.f;
        if (k < RDIM * PDIM)
            v = __ldg(&M[(size_t)((l * RDIM + k / PDIM) * PDIM + k % PDIM) * HDIM + h]);
        B[i] = __float2bfloat16(v);
    }
}

// ---------------- smem-staged single-pass node scan + zero cnt + node-0 eproba ----------------
__global__ void __launch_bounds__(1024) k_scanall(
    int* __restrict__ cnt, int* __restrict__ off,
    const float* __restrict__ proto0, const float* __restrict__ semb,
    float* __restrict__ eproba, int E)
{
    extern __shared__ int sc[];                // NNODES ints (200 KB)
    __shared__ int wsum[32];
    const int PER = (NNODES + 1023) / 1024;    // 49
    int tid = threadIdx.x, lane = tid & 31, wid = tid >> 5;

    #pragma unroll
    for (int r = 0; r < PER; r++) {
        int i = r * 1024 + tid;
        if (i < NNODES) sc[i] = cnt[i];
    }
    __syncthreads();

    int base = tid * PER;
    int lsum = 0;
    #pragma unroll 7
    for (int k = 0; k < PER; k++) {
        int i = base + k;
        if (i < NNODES) lsum += sc[i];
    }
    int x = lsum;
    #pragma unroll
    for (int o = 1; o < 32; o <<= 1) {
        int y = __shfl_up_sync(0xffffffffu, x, o);
        if (lane >= o) x += y;
    }
    if (lane == 31) wsum[wid] = x;
    __syncthreads();
    if (wid == 0) {
        int wv = wsum[lane];
        #pragma unroll
        for (int o = 1; o < 32; o <<= 1) {
            int y = __shfl_up_sync(0xffffffffu, wv, o);
            if (lane >= o) wv += y;
        }
        wsum[lane] = wv;
    }
    __syncthreads();
    int pfx = ((wid > 0) ? wsum[wid - 1] : 0) + x - lsum;
    #pragma unroll 7
    for (int k = 0; k < PER; k++) {
        int i = base + k;
        if (i < NNODES) { int v = sc[i]; sc[i] = pfx; pfx += v; }
    }
    __syncthreads();
    #pragma unroll
    for (int r = 0; r < PER; r++) {
        int i = r * 1024 + tid;
        if (i < NNODES) { off[i] = sc[i]; cnt[i] = 0; }
    }
    if (tid == 0) off[NNODES] = E;

    // node 0: real eproba row from semb vs layer-0 protos (warp 0)
    if (wid == 0) {
        float4 h = ((const float4*)semb)[lane];
        float ss = h.x * h.x + h.y * h.y + h.z * h.z + h.w * h.w;
        #pragma unroll
        for (int o = 16; o; o >>= 1) ss += __shfl_xor_sync(0xffffffffu, ss, o);
        float inv = 1.f / fmaxf(sqrtf(ss), 1e-12f);
        float d[PDIM];
        #pragma unroll
        for (int p = 0; p < PDIM; p++) {
            float4 q = ((const float4*)(proto0 + p * HDIM))[lane];
            float sp = q.x * q.x + q.y * q.y + q.z * q.z + q.w * q.w;
            float dp = h.x * q.x + h.y * q.y + h.z * q.z + h.w * q.w;
            #pragma unroll
            for (int o = 16; o; o >>= 1) {
                sp += __shfl_xor_sync(0xffffffffu, sp, o);
                dp += __shfl_xor_sync(0xffffffffu, dp, o);
            }
            d[p] = dp * inv / fmaxf(sqrtf(sp), 1e-12f);
        }
        float mx = -1e30f;
        #pragma unroll
        for (int p = 0; p < PDIM; p++) mx = fmaxf(mx, d[p]);
        float sum = 0.f;
        #pragma unroll
        for (int p = 0; p < PDIM; p++) { d[p] = expf(d[p] - mx); sum += d[p]; }
        float rs = 1.f / sum;
        float ent = 0.f;
        #pragma unroll
        for (int p = 0; p < PDIM; p++) { d[p] *= rs; ent -= d[p] * logf(d[p] + 1e-8f); }
        float exl = expf(-ent);
        if (lane == 0) {
            #pragma unroll
            for (int p = 0; p < PDIM; p++) eproba[p] = d[p] * exl;
            #pragma unroll
            for (int p = PDIM; p < 31; p++) eproba[p] = 0.f;
            eproba[31] = exl;
        }
    }
}

// ---------------- off2: warp per node, bucket offsets + zero cnt2/run2 ----------------
__global__ void __launch_bounds__(256) k_off2(
    const int* __restrict__ off, int* __restrict__ cnt2, int* __restrict__ run2,
    int* __restrict__ off2, int E)
{
    int w = (blockIdx.x * blockDim.x + threadIdx.x) >> 5;
    int lane = threadIdx.x & 31;
    if (w >= NNODES) return;
    int idx = w * RDIM + lane;
    int c = (lane < RDIM) ? cnt2[idx] : 0;
    // exclusive warp scan of c over lanes 0..17
    int x = c;
    #pragma unroll
    for (int o = 1; o < 32; o <<= 1) {
        int y = __shfl_up_sync(0xffffffffu, x, o);
        if (lane >= o) x += y;
    }
    int base = __ldg(&off[w]);
    if (lane < RDIM) {
        off2[idx] = base + x - c;
        cnt2[idx] = 0;
        run2[idx] = 0;
    }
    if (w == 0 && lane == 0) off2[NB2] = E;
}

// ---------------- rank: scatter into (dst,r)-sorted order, pack (src<<5)|r ----------------
__global__ void k_rank(const int* __restrict__ dst, const int* __restrict__ et,
                       const int* __restrict__ src,
                       const int* __restrict__ off2, int* __restrict__ run2,
                       int* __restrict__ srcs, int E) {
    int e = blockIdx.x * blockDim.x + threadIdx.x;
    if (e >= E) return;
    int r = et[e];
    int b = dst[e] * RDIM + r;
    int pos = off2[b] + atomicAdd(&run2[b], 1);
    srcs[pos] = (src[e] << 5) | r;
}

// ---------------- build W layer 0: run-length, constant eproba, no gathers ----------------
__global__ void __launch_bounds__(256) k_build_W0(
    const int* __restrict__ srcs, const int* __restrict__ off,
    const float* __restrict__ eproba,
    __nv_bfloat16* __restrict__ A, float* __restrict__ rden)
{
    int w = (blockIdx.x * blockDim.x + threadIdx.x) >> 5;
    int lane = threadIdx.x & 31;
    if (w >= NNODES) return;
    size_t rowoff = (size_t)w * KUF;
    int beg = __ldg(&off[w]);
    int end = __ldg(&off[w + 1]);
    const __nv_bfloat16 bz = __float2bfloat16(0.f);

    if (lane < KUF - RDIM * PDIM)
        A[rowoff + RDIM * PDIM + lane] = bz;

    const float pu = 1.f / 18.f;
    const float exlu = pu + 1e-8f;
    const float eb = (lane < PDIM) ? pu * exlu : ((lane == 31) ? exlu : 0.f);
    const float sp = __ldg(&eproba[lane]);     // node-0 row

    int cur = 0;
    float acc = 0.f, den = 0.f;
    for (int j = beg; j < end; j++) {
        unsigned pk = (unsigned)__ldg(&srcs[j]);
        int r = (int)(pk & 31u);
        if (r != cur) {
            den += acc;
            if (lane < PDIM) A[rowoff + cur * PDIM + lane] = __float2bfloat16(acc);
            for (cur++; cur < r; cur++)
                if (lane < PDIM) A[rowoff + cur * PDIM + lane] = bz;
            acc = 0.f;
        }
        acc += ((pk & ~31u) == 0u) ? sp : eb;
    }
    den += acc;
    if (lane < PDIM) A[rowoff + cur * PDIM + lane] = __float2bfloat16(acc);
    for (cur++; cur < RDIM; cur++)
        if (lane < PDIM) A[rowoff + cur * PDIM + lane] = bz;
    if (lane == 31) rden[w] = (beg == end) ? 0.f : (1.f / den);
}

// ---------------- build W general: run-length register accumulate, no smem ----------------
__global__ void __launch_bounds__(256) k_build_W(
    const int* __restrict__ srcs, const int* __restrict__ off,
    const float* __restrict__ eproba,
    __nv_bfloat16* __restrict__ A, float* __restrict__ rden)
{
    int w = (blockIdx.x * blockDim.x + threadIdx.x) >> 5;
    int lane = threadIdx.x & 31;
    if (w >= NNODES) return;
    size_t rowoff = (size_t)w * KUF;
    int beg = __ldg(&off[w]);
    int end = __ldg(&off[w + 1]);
    const __nv_bfloat16 bz = __float2bfloat16(0.f);

    if (lane < KUF - RDIM * PDIM)
        A[rowoff + RDIM * PDIM + lane] = bz;

    int cur = 0;
    float acc = 0.f, den = 0.f;
    for (int j = beg; j < end; j++) {
        unsigned pk = (unsigned)__ldg(&srcs[j]);
        int r = (int)(pk & 31u);
        if (r != cur) {
            den += acc;
            if (lane < PDIM) A[rowoff + cur * PDIM + lane] = __float2bfloat16(acc);
            for (cur++; cur < r; cur++)
                if (lane < PDIM) A[rowoff + cur * PDIM + lane] = bz;
            acc = 0.f;
        }
        acc += __ldg(&eproba[(pk & ~31u) + lane]);
    }
    den += acc;
    if (lane < PDIM) A[rowoff + cur * PDIM + lane] = __float2bfloat16(acc);
    for (cur++; cur < RDIM; cur++)
        if (lane < PDIM) A[rowoff + cur * PDIM + lane] = bz;
    if (lane == 31) rden[w] = (beg == end) ? 0.f : (1.f / den);
}

// ---------------- bf16 GEMM + fused next-layer logits epilogue ----------------
__global__ void __launch_bounds__(256) k_gemm(
    const __nv_bfloat16* __restrict__ A_, const __nv_bfloat16* __restrict__ B_,
    const float* __restrict__ rden,
    const float* __restrict__ proto_next,
    float* __restrict__ ep_out,
    float* __restrict__ hid_out)
{
    extern __shared__ unsigned sm[];
    int tid = threadIdx.x;
    int wid = tid >> 5, lane = tid & 31;
    int wm = wid & 3, wn = wid >> 2;
    int g = lane >> 2, t = lane & 3;
    int rowbase = blockIdx.x * 128;

    if (ep_out) proto_to_smem(proto_next, (float*)sm + PS_OFF);

    const unsigned* Ag = (const unsigned*)A_;
    const unsigned* Bg = (const unsigned*)B_;

    float acc[2][8][4];
    #pragma unroll
    for (int mt = 0; mt < 2; mt++)
        #pragma unroll
        for (int nt = 0; nt < 8; nt++)
            #pragma unroll
            for (int c = 0; c < 4; c++) acc[mt][nt][c] = 0.f;

    const int STAGE = 2 * 128 * SMS;

    auto load_stage = [&](int stage, int kc) {
        unsigned* sb = sm + stage * STAGE;
        int kb = kc * 16;
        #pragma unroll
        for (int i = 0; i < 2; i++) {
            int q = i * 256 + tid;
            int row = q >> 2;
            int c4 = (q & 3) * 4;
            cp_async16(sb + row * SMS + c4, Ag + (size_t)(rowbase + row) * KU32 + kb + c4);
            cp_async16(sb + 128 * SMS + row * SMS + c4, Bg + (size_t)row * KU32 + kb + c4);
        }
        CP_COMMIT();
    };

    load_stage(0, 0);

    #pragma unroll 1
    for (int kc = 0; kc < NCH; kc++) {
        int cur = kc & 1;
        if (kc + 1 < NCH) { load_stage(cur ^ 1, kc + 1); CP_WAIT(1); }
        else              { CP_WAIT(0); }
        __syncthreads();

        unsigned* As = sm + cur * STAGE;
        unsigned* Bs = As + 128 * SMS;

        #pragma unroll
        for (int ks = 0; ks < 2; ks++) {
            int kb8 = ks * 8;
            unsigned a[2][4];
            #pragma unroll
            for (int mt = 0; mt < 2; mt++) {
                int mr = wm * 32 + mt * 16 + g;
                a[mt][0] = As[mr * SMS + kb8 + t];
                a[mt][1] = As[(mr + 8) * SMS + kb8 + t];
                a[mt][2] = As[mr * SMS + kb8 + t + 4];
                a[mt][3] = As[(mr + 8) * SMS + kb8 + t + 4];
            }
            #pragma unroll
            for (int nt = 0; nt < 8; nt++) {
                int nr = wn * 64 + nt * 8 + g;
                unsigned b[2];
                b[0] = Bs[nr * SMS + kb8 + t];
                b[1] = Bs[nr * SMS + kb8 + t + 4];
                #pragma unroll
                for (int mt = 0; mt < 2; mt++) mma_bf16(acc[mt][nt], a[mt], b);
            }
        }
        __syncthreads();
    }

    if (ep_out == nullptr) {
        #pragma unroll
        for (int mt = 0; mt < 2; mt++) {
            int r0 = rowbase + wm * 32 + mt * 16 + g;
            int r1 = r0 + 8;
            float s0v = (r0 < NNODES) ? __ldg(&rden[r0]) : 0.f;
            float s1v = (r1 < NNODES) ? __ldg(&rden[r1]) : 0.f;
            #pragma unroll
            for (int nt = 0; nt < 8; nt++) {
                int col = wn * 64 + nt * 8 + t * 2;
                if (r0 < NNODES)
                    *(float2*)(hid_out + (size_t)r0 * HDIM + col) =
                        make_float2(acc[mt][nt][0] * s0v, acc[mt][nt][1] * s0v);
                if (r1 < NNODES)
                    *(float2*)(hid_out + (size_t)r1 * HDIM + col) =
                        make_float2(acc[mt][nt][2] * s1v, acc[mt][nt][3] * s1v);
            }
        }
        return;
    }

    // fused logits: stage scaled C tile into smem (pipeline area is dead)
    float* ct = (float*)sm;
    #pragma unroll
    for (int mt = 0; mt < 2; mt++) {
        int r0l = wm * 32 + mt * 16 + g;
        int r1l = r0l + 8;
        int gr0 = rowbase + r0l, gr1 = rowbase + r1l;
        float s0v = (gr0 < NNODES) ? __ldg(&rden[gr0]) : 0.f;
        float s1v = (gr1 < NNODES) ? __ldg(&rden[gr1]) : 0.f;
        #pragma unroll
        for (int nt = 0; nt < 8; nt++) {
            int col = wn * 64 + nt * 8 + t * 2;
            ct[r0l * CTS + col]     = acc[mt][nt][0] * s0v;
            ct[r0l * CTS + col + 1] = acc[mt][nt][1] * s0v;
            ct[r1l * CTS + col]     = acc[mt][nt][2] * s1v;
            ct[r1l * CTS + col + 1] = acc[mt][nt][3] * s1v;
        }
    }
    __syncthreads();

    if (tid < 128) {
        int row = tid;
        int gr = rowbase + row;
        if (gr < NNODES) {
            const float* hr  = ct + row * CTS;
            const float* psn = (const float*)sm + PS_OFF;
            float ss = 0.f;
            float d[PDIM];
            #pragma unroll
            for (int p = 0; p < PDIM; p++) d[p] = 0.f;
            #pragma unroll 4
            for (int i = 0; i < HDIM; i++) {
                float hv = hr[i];
                ss += hv * hv;
                #pragma unroll
                for (int p = 0; p < PDIM; p++) d[p] += hv * psn[p * HDIM + i];
            }
            float inv = 1.f / fmaxf(sqrtf(ss), 1e-12f);
            float mx = -1e30f;
            #pragma unroll
            for (int p = 0; p < PDIM; p++) { d[p] *= inv; mx = fmaxf(mx, d[p]); }
            float sum = 0.f;
            #pragma unroll
            for (int p = 0; p < PDIM; p++) { d[p] = expf(d[p] - mx); sum += d[p]; }
            float rs = 1.f / sum;
            float ent = 0.f;
            #pragma unroll
            for (int p = 0; p < PDIM; p++) { d[p] *= rs; ent -= d[p] * logf(d[p] + 1e-8f); }
            float exl = expf(-ent);
            float vals[32];
            #pragma unroll
            for (int p = 0; p < PDIM; p++) vals[p] = d[p] * exl;
            #pragma unroll
            for (int p = PDIM; p < 31; p++) vals[p] = 0.f;
            vals[31] = exl;
            float4* dp4 = (float4*)(ep_out + (size_t)gr * PSTRIDE);
            #pragma unroll
            for (int q = 0; q < 8; q++)
                dp4[q] = make_float4(vals[q * 4], vals[q * 4 + 1],
                                     vals[q * 4 + 2], vals[q * 4 + 3]);
        }
    }
}

// ---------------- classifier ----------------
__global__ void __launch_bounds__(128) k_classifier(
    const float* __restrict__ hidden, const int* __restrict__ tails,
    const float* __restrict__ proto, float* __restrict__ out, int B)
{
    __shared__ float ps[PDIM * HDIM];
    proto_to_smem(proto, ps);
    int t = blockIdx.x * blockDim.x + threadIdx.x;
    if (t >= B) return;
    const float4* hp = (const float4*)(hidden + (size_t)__ldg(&tails[t]) * HDIM);
    float d[PDIM];
    #pragma unroll
    for (int p = 0; p < PDIM; p++) d[p] = 0.f;
    float ss = 0.f;
    for (int i = 0; i < HDIM / 4; i++) {
        float4 h = __ldg(hp + i);
        ss += h.x * h.x + h.y * h.y + h.z * h.z + h.w * h.w;
        #pragma unroll
        for (int p = 0; p < PDIM; p++) {
            float4 q = *(const float4*)(ps + p * HDIM + i * 4);
            d[p] += h.x * q.x + h.y * q.y + h.z * q.z + h.w * q.w;
        }
    }
    float inv = 1.f / fmaxf(sqrtf(ss), 1e-12f);
    #pragma unroll
    for (int p = 0; p < PDIM; p++) out[(size_t)t * PDIM + p] = d[p] * inv;
}

// ---------------- host ----------------
static inline int grd(int n, int b) { return (n + b - 1) / b; }

extern "C" void kernel_launch(void* const* d_in, const int* in_sizes, int n_in,
                              void* d_out, int out_size)
{
    const int*   edge_index = (const int*)d_in[0];
    const int*   etype      = (const int*)d_in[1];
    const int*   tails      = (const int*)d_in[2];
    const float* multi      = (const float*)d_in[3];
    const float* proto      = (const float*)d_in[4];
    const float* semb       = (const float*)d_in[5];
    float* out = (float*)d_out;

    int E = in_sizes[0] / 2;
    int B = in_sizes[2];
    int L = in_sizes[3] / (RDIM * PDIM * HDIM);
    const int* src = edge_index;
    const int* dst = edge_index + E;

    float *hid, *rden, *eproba;
    __nv_bfloat16 *A, *Bm;
    int *cnt, *cnt2, *run2, *off, *off2, *srcs;
    cudaGetSymbolAddress((void**)&hid,    g_hidden);
    cudaGetSymbolAddress((void**)&eproba, g_eproba);
    cudaGetSymbolAddress((void**)&rden,   g_rden);
    cudaGetSymbolAddress((void**)&A,      g_A);
    cudaGetSymbolAddress((void**)&Bm,     g_B);
    cudaGetSymbolAddress((void**)&cnt,    g_cnt);
    cudaGetSymbolAddress((void**)&cnt2,   g_cnt2);
    cudaGetSymbolAddress((void**)&run2,   g_run2);
    cudaGetSymbolAddress((void**)&off,    g_off);
    cudaGetSymbolAddress((void**)&off2,   g_off2);
    cudaGetSymbolAddress((void**)&srcs,   g_srcs);

    const int TB = 256;
    const int SM_PLAIN = 2 * 2 * 128 * SMS * 4;             // 40960
    const int SM_FUSED = (PS_OFF + PDIM * HDIM) * 4;        // 75264
    const int SM_SCAN  = NNODES * 4;                        // 200000
    cudaFuncSetAttribute(k_gemm, cudaFuncAttributeMaxDynamicSharedMemorySize, SM_FUSED);
    cudaFuncSetAttribute(k_scanall, cudaFuncAttributeMaxDynamicSharedMemorySize, SM_SCAN);

    // ---- preprocessing (cnt/cnt2/run2 are zero from init / previous run) ----
    k_setup<<<grd(E, TB), TB>>>(dst, etype, cnt, cnt2, E, A, multi, Bm, L * 128 * KUF);
    k_scanall<<<1, 1024, SM_SCAN>>>(cnt, off, proto, semb, eproba, E);
    k_off2<<<grd(NNODES * 32, TB), TB>>>(off, cnt2, run2, off2, E);
    k_rank<<<grd(E, TB), TB>>>(dst, etype, src, off2, run2, srcs, E);

    for (int l = 0; l < L; l++) {
        bool last = (l == L - 1);
        if (l == 0)
            k_build_W0<<<grd(NNODES * 32, TB), TB>>>(srcs, off, eproba, A, rden);
        else
            k_build_W<<<grd(NNODES * 32, TB), TB>>>(srcs, off, eproba, A, rden);
        k_gemm<<<NTILES, 256, last ? SM_PLAIN : SM_FUSED>>>(
            A, Bm + (size_t)l * 128 * KUF, rden,
            last ? nullptr : proto + (size_t)(l + 1) * PDIM * HDIM,
            last ? nullptr : eproba,
            last ? hid : nullptr);
    }

    k_classifier<<<grd(B, 128), 128>>>(
        hid, tails, proto + (size_t)(L - 1) * PDIM * HDIM, out, B);
}

// round 16
// speedup vs baseline: 1.2494x; 1.2494x over previous
#include <cuda_runtime.h>
#include <cuda_bf16.h>
#include <cstdint>

#define HDIM 128
#define PDIM 18
#define RDIM 18
#define NNODES 50000
#define NTILES 391
#define NROWS (NTILES * 128)     // 50048
#define MAXE 800000
#define PSTRIDE 32               // eproba row stride (f32)
#define KUF 352                  // K padded (bf16 elems per row)
#define KU32 176                 // u32 (bf16x2) per row
#define NCH 11                   // k chunks of 32 bf16 (16 u32)
#define SMS 20                   // pipeline smem row stride in u32
#define CTS 129                  // epilogue C-tile stride (f32)
#define PS_OFF 16512             // f32 offset of protos in gemm smem (128*129)
#define WST 33                   // build_W slab stride (bank-staggered)
#define LMAX 3

// ---------------- scratch (device globals; no allocations allowed) ----------------
__device__ float         g_hidden[NNODES * HDIM];     // last-layer output only
__device__ float         g_eproba[NNODES * PSTRIDE];  // [n][p]=exl*proba, [n][31]=exl
__device__ float         g_rden[NNODES];
__device__ __nv_bfloat16 g_A[(size_t)NROWS * KUF];
__device__ __nv_bfloat16 g_B[LMAX * 128 * KUF];
__device__ int           g_cnt[NNODES];               // zero at init; re-zeroed by scanall
__device__ int           g_run[NNODES];               // zero at init; re-zeroed by scanall
__device__ int           g_off[NNODES + 1];
__device__ int           g_srcs[MAXE];                // packed (r<<26)|(src<<5), sorted by dst

// ---------------- helpers ----------------
__device__ __forceinline__ void cp_async16(void* sdst, const void* gsrc) {
    unsigned s = (unsigned)__cvta_generic_to_shared(sdst);
    asm volatile("cp.async.cg.shared.global [%0], [%1], 16;\n" :: "r"(s), "l"(gsrc));
}
#define CP_COMMIT() asm volatile("cp.async.commit_group;\n" ::: "memory")
#define CP_WAIT(n)  asm volatile("cp.async.wait_group %0;\n" :: "n"(n) : "memory")

__device__ __forceinline__ void mma_bf16(float* c, const unsigned* a, const unsigned* b) {
    asm volatile(
        "mma.sync.aligned.m16n8k16.row.col.f32.bf16.bf16.f32 "
        "{%0,%1,%2,%3}, {%4,%5,%6,%7}, {%8,%9}, {%0,%1,%2,%3};\n"
        : "+f"(c[0]), "+f"(c[1]), "+f"(c[2]), "+f"(c[3])
        : "r"(a[0]), "r"(a[1]), "r"(a[2]), "r"(a[3]), "r"(b[0]), "r"(b[1]));
}

// vectorized slab->A writeback: 162 u32 (324 bf16), q=(r,p) via mul-shift /18
__device__ __forceinline__ void writeback_W(
    const float* W, __nv_bfloat16* A, size_t rowoff, int lane)
{
    uint32_t* Arow = (uint32_t*)(A + rowoff);
    for (int i = lane; i < 162; i += 32) {
        int q0 = i * 2;
        int r0 = (q0 * 57) >> 10;           // q0/18, exact for q0<324
        int p0 = q0 - r0 * 18;
        float v0 = W[r0 * WST + p0];
        float v1 = (p0 == 17) ? W[(r0 + 1) * WST] : W[r0 * WST + p0 + 1];
        __nv_bfloat162 tt = __floats2bfloat162_rn(v0, v1);
        Arow[i] = *(uint32_t*)&tt;
    }
    if (lane < KU32 - 162) Arow[162 + lane] = 0;   // pad columns 324..351
}

// normalize PDIM proto rows into smem ps[]
__device__ __forceinline__ void proto_to_smem(const float* __restrict__ proto, float* ps) {
    int warp = threadIdx.x >> 5, lane = threadIdx.x & 31;
    int nw = blockDim.x >> 5;
    for (int p = warp; p < PDIM; p += nw) {
        float4 v = ((const float4*)(proto + p * HDIM))[lane];
        float ss = v.x * v.x + v.y * v.y + v.z * v.z + v.w * v.w;
        #pragma unroll
        for (int o = 16; o; o >>= 1) ss += __shfl_xor_sync(0xffffffffu, ss, o);
        float inv = 1.f / fmaxf(sqrtf(ss), 1e-12f);
        ((float4*)(ps + p * HDIM))[lane] = make_float4(v.x * inv, v.y * inv, v.z * inv, v.w * inv);
    }
    __syncthreads();
}

// ---------------- setup (cnt assumed zero): hist + A pad + B build ----------------
__global__ void k_setup(const int* __restrict__ dst, int* __restrict__ cnt, int E,
                        __nv_bfloat16* __restrict__ A,
                        const float* __restrict__ M, __nv_bfloat16* __restrict__ B,
                        int btotal) {
    int i = blockIdx.x * blockDim.x + threadIdx.x;
    if (i < E) atomicAdd(&cnt[dst[i]], 1);
    if (i < (NROWS - NNODES) * KUF)
        A[(size_t)NNODES * KUF + i] = __float2bfloat16(0.f);
    if (i < btotal) {                          // B[l][h][k] = bf16(M[l][k/18][k%18][h])
        int l = i / (128 * KUF);
        int rem = i - l * 128 * KUF;
        int h = rem / KUF, k = rem % KUF;
        float v = 0.f;
        if (k < RDIM * PDIM)
            v = __ldg(&M[(size_t)((l * RDIM + k / PDIM) * PDIM + k % PDIM) * HDIM + h]);
        B[i] = __float2bfloat16(v);
    }
}

// ---------------- smem-staged single-pass scan + re-zero cnt/run + node-0 eproba ----------------
__global__ void __launch_bounds__(1024) k_scanall(
    int* __restrict__ cnt, int* __restrict__ run, int* __restrict__ off,
    const float* __restrict__ proto0, const float* __restrict__ semb,
    float* __restrict__ eproba, int E)
{
    extern __shared__ int sc[];                // NNODES ints (200 KB)
    __shared__ int wsum[32];
    const int PER = (NNODES + 1023) / 1024;    // 49
    int tid = threadIdx.x, lane = tid & 31, wid = tid >> 5;

    #pragma unroll
    for (int r = 0; r < PER; r++) {
        int i = r * 1024 + tid;
        if (i < NNODES) sc[i] = cnt[i];
    }
    __syncthreads();

    int base = tid * PER;
    int lsum = 0;
    #pragma unroll 7
    for (int k = 0; k < PER; k++) {
        int i = base + k;
        if (i < NNODES) lsum += sc[i];
    }
    int x = lsum;
    #pragma unroll
    for (int o = 1; o < 32; o <<= 1) {
        int y = __shfl_up_sync(0xffffffffu, x, o);
        if (lane >= o) x += y;
    }
    if (lane == 31) wsum[wid] = x;
    __syncthreads();
    if (wid == 0) {
        int wv = wsum[lane];
        #pragma unroll
        for (int o = 1; o < 32; o <<= 1) {
            int y = __shfl_up_sync(0xffffffffu, wv, o);
            if (lane >= o) wv += y;
        }
        wsum[lane] = wv;
    }
    __syncthreads();
    int pfx = ((wid > 0) ? wsum[wid - 1] : 0) + x - lsum;
    #pragma unroll 7
    for (int k = 0; k < PER; k++) {
        int i = base + k;
        if (i < NNODES) { int v = sc[i]; sc[i] = pfx; pfx += v; }
    }
    __syncthreads();
    #pragma unroll
    for (int r = 0; r < PER; r++) {
        int i = r * 1024 + tid;
        if (i < NNODES) { off[i] = sc[i]; cnt[i] = 0; run[i] = 0; }
    }
    if (tid == 0) off[NNODES] = E;

    // node 0: real eproba row from semb vs layer-0 protos (warp 0)
    if (wid == 0) {
        float4 h = ((const float4*)semb)[lane];
        float ss = h.x * h.x + h.y * h.y + h.z * h.z + h.w * h.w;
        #pragma unroll
        for (int o = 16; o; o >>= 1) ss += __shfl_xor_sync(0xffffffffu, ss, o);
        float inv = 1.f / fmaxf(sqrtf(ss), 1e-12f);
        float d[PDIM];
        #pragma unroll
        for (int p = 0; p < PDIM; p++) {
            float4 q = ((const float4*)(proto0 + p * HDIM))[lane];
            float sp = q.x * q.x + q.y * q.y + q.z * q.z + q.w * q.w;
            float dp = h.x * q.x + h.y * q.y + h.z * q.z + h.w * q.w;
            #pragma unroll
            for (int o = 16; o; o >>= 1) {
                sp += __shfl_xor_sync(0xffffffffu, sp, o);
                dp += __shfl_xor_sync(0xffffffffu, dp, o);
            }
            d[p] = dp * inv / fmaxf(sqrtf(sp), 1e-12f);
        }
        float mx = -1e30f;
        #pragma unroll
        for (int p = 0; p < PDIM; p++) mx = fmaxf(mx, d[p]);
        float sum = 0.f;
        #pragma unroll
        for (int p = 0; p < PDIM; p++) { d[p] = expf(d[p] - mx); sum += d[p]; }
        float rs = 1.f / sum;
        float ent = 0.f;
        #pragma unroll
        for (int p = 0; p < PDIM; p++) { d[p] *= rs; ent -= d[p] * logf(d[p] + 1e-8f); }
        float exl = expf(-ent);
        if (lane == 0) {
            #pragma unroll
            for (int p = 0; p < PDIM; p++) eproba[p] = d[p] * exl;
            #pragma unroll
            for (int p = PDIM; p < 31; p++) eproba[p] = 0.f;
            eproba[31] = exl;
        }
    }
}

// ---------------- rank: pack (r<<26) | (src<<5) ----------------
__global__ void k_rank(const int* __restrict__ dst, const int* __restrict__ et,
                       const int* __restrict__ src,
                       const int* __restrict__ off, int* __restrict__ run,
                       int* __restrict__ srcs, int E) {
    int e = blockIdx.x * blockDim.x + threadIdx.x;
    if (e >= E) return;
    int d = dst[e];
    int pos = off[d] + atomicAdd(&run[d], 1);
    srcs[pos] = (et[e] << 26) | (src[e] << 5);
}

// ---------------- build W layer 0: constant eproba, gather-free, slab stride 33 ----------------
__global__ void __launch_bounds__(256) k_build_W0(
    const int* __restrict__ srcs, const int* __restrict__ off,
    const float* __restrict__ eproba,
    __nv_bfloat16* __restrict__ A, float* __restrict__ rden)
{
    __shared__ float sW[8][RDIM * WST];
    int w = (blockIdx.x * blockDim.x + threadIdx.x) >> 5;
    int wl = (threadIdx.x >> 5);
    int lane = threadIdx.x & 31;
    if (w >= NNODES) return;
    float* W = sW[wl];
    size_t rowoff = (size_t)w * KUF;
    int beg = __ldg(&off[w]);
    int end = __ldg(&off[w + 1]);

    #pragma unroll
    for (int r = 0; r < RDIM; r++) W[r * WST + lane] = 0.f;

    const float pu = 1.f / 18.f;
    const float exlu = pu + 1e-8f;
    const float eb = (lane < PDIM) ? pu * exlu : ((lane == 31) ? exlu : 0.f);
    const float sp = __ldg(&eproba[lane]);     // node-0 row

    float den = 0.f;
    for (int j = beg; j < end; j++) {
        unsigned pk = (unsigned)__ldg(&srcs[j]);
        float e = ((pk & 0x03FFFFFFu) == 0u) ? sp : eb;
        den += e;
        W[(pk >> 26) * WST + lane] += e;
    }

    writeback_W(W, A, rowoff, lane);
    if (lane == 31) rden[w] = (beg == end) ? 0.f : (1.f / den);
}

// ---------------- build W general: slab stride 33, int4 ILP-8, vectorized writeback ----------------
__global__ void __launch_bounds__(256) k_build_W(
    const int* __restrict__ srcs, const int* __restrict__ off,
    const float* __restrict__ eproba,
    __nv_bfloat16* __restrict__ A, float* __restrict__ rden)
{
    __shared__ float sW[8][RDIM * WST];
    int w = (blockIdx.x * blockDim.x + threadIdx.x) >> 5;
    int wl = (threadIdx.x >> 5);
    int lane = threadIdx.x & 31;
    if (w >= NNODES) return;
    float* W = sW[wl];
    size_t rowoff = (size_t)w * KUF;
    int beg = __ldg(&off[w]);
    int end = __ldg(&off[w + 1]);

    #pragma unroll
    for (int r = 0; r < RDIM; r++) W[r * WST + lane] = 0.f;

    float den = 0.f;
    int j = beg;
    int alim = (beg + 3) & ~3;
    if (alim > end) alim = end;
    for (; j < alim; j++) {                   // head peel to 16B alignment
        unsigned pk = (unsigned)__ldg(&srcs[j]);
        float e0 = __ldg(&eproba[(pk & 0x03FFFFFFu) + lane]);
        den += e0;
        W[(pk >> 26) * WST + lane] += e0;
    }
    for (; j + 7 < end; j += 8) {             // aligned int4 x2 main loop (ILP-8)
        int4 pa = *(const int4*)(srcs + j);
        int4 pb = *(const int4*)(srcs + j + 4);
        float e0 = __ldg(&eproba[((unsigned)pa.x & 0x03FFFFFFu) + lane]);
        float e1 = __ldg(&eproba[((unsigned)pa.y & 0x03FFFFFFu) + lane]);
        float e2 = __ldg(&eproba[((unsigned)pa.z & 0x03FFFFFFu) + lane]);
        float e3 = __ldg(&eproba[((unsigned)pa.w & 0x03FFFFFFu) + lane]);
        float e4 = __ldg(&eproba[((unsigned)pb.x & 0x03FFFFFFu) + lane]);
        float e5 = __ldg(&eproba[((unsigned)pb.y & 0x03FFFFFFu) + lane]);
        float e6 = __ldg(&eproba[((unsigned)pb.z & 0x03FFFFFFu) + lane]);
        float e7 = __ldg(&eproba[((unsigned)pb.w & 0x03FFFFFFu) + lane]);
        den += (e0 + e1) + (e2 + e3) + (e4 + e5) + (e6 + e7);
        W[((unsigned)pa.x >> 26) * WST + lane] += e0;
        W[((unsigned)pa.y >> 26) * WST + lane] += e1;
        W[((unsigned)pa.z >> 26) * WST + lane] += e2;
        W[((unsigned)pa.w >> 26) * WST + lane] += e3;
        W[((unsigned)pb.x >> 26) * WST + lane] += e4;
        W[((unsigned)pb.y >> 26) * WST + lane] += e5;
        W[((unsigned)pb.z >> 26) * WST + lane] += e6;
        W[((unsigned)pb.w >> 26) * WST + lane] += e7;
    }
    for (; j + 3 < end; j += 4) {             // int4 cleanup
        int4 pa = *(const int4*)(srcs + j);
        float e0 = __ldg(&eproba[((unsigned)pa.x & 0x03FFFFFFu) + lane]);
        float e1 = __ldg(&eproba[((unsigned)pa.y & 0x03FFFFFFu) + lane]);
        float e2 = __ldg(&eproba[((unsigned)pa.z & 0x03FFFFFFu) + lane]);
        float e3 = __ldg(&eproba[((unsigned)pa.w & 0x03FFFFFFu) + lane]);
        den += (e0 + e1) + (e2 + e3);
        W[((unsigned)pa.x >> 26) * WST + lane] += e0;
        W[((unsigned)pa.y >> 26) * WST + lane] += e1;
        W[((unsigned)pa.z >> 26) * WST + lane] += e2;
        W[((unsigned)pa.w >> 26) * WST + lane] += e3;
    }
    for (; j < end; j++) {                    // tail
        unsigned pk = (unsigned)__ldg(&srcs[j]);
        float e0 = __ldg(&eproba[(pk & 0x03FFFFFFu) + lane]);
        den += e0;
        W[(pk >> 26) * WST + lane] += e0;
    }

    writeback_W(W, A, rowoff, lane);
    if (lane == 31) rden[w] = (beg == end) ? 0.f : (1.f / den);
}

// ---------------- bf16 GEMM + fused next-layer logits epilogue ----------------
__global__ void __launch_bounds__(256) k_gemm(
    const __nv_bfloat16* __restrict__ A_, const __nv_bfloat16* __restrict__ B_,
    const float* __restrict__ rden,
    const float* __restrict__ proto_next,
    float* __restrict__ ep_out,
    float* __restrict__ hid_out)
{
    extern __shared__ unsigned sm[];
    int tid = threadIdx.x;
    int wid = tid >> 5, lane = tid & 31;
    int wm = wid & 3, wn = wid >> 2;
    int g = lane >> 2, t = lane & 3;
    int rowbase = blockIdx.x * 128;

    if (ep_out) proto_to_smem(proto_next, (float*)sm + PS_OFF);

    const unsigned* Ag = (const unsigned*)A_;
    const unsigned* Bg = (const unsigned*)B_;

    float acc[2][8][4];
    #pragma unroll
    for (int mt = 0; mt < 2; mt++)
        #pragma unroll
        for (int nt = 0; nt < 8; nt++)
            #pragma unroll
            for (int c = 0; c < 4; c++) acc[mt][nt][c] = 0.f;

    const int STAGE = 2 * 128 * SMS;

    auto load_stage = [&](int stage, int kc) {
        unsigned* sb = sm + stage * STAGE;
        int kb = kc * 16;
        #pragma unroll
        for (int i = 0; i < 2; i++) {
            int q = i * 256 + tid;
            int row = q >> 2;
            int c4 = (q & 3) * 4;
            cp_async16(sb + row * SMS + c4, Ag + (size_t)(rowbase + row) * KU32 + kb + c4);
            cp_async16(sb + 128 * SMS + row * SMS + c4, Bg + (size_t)row * KU32 + kb + c4);
        }
        CP_COMMIT();
    };

    load_stage(0, 0);

    #pragma unroll 1
    for (int kc = 0; kc < NCH; kc++) {
        int cur = kc & 1;
        if (kc + 1 < NCH) { load_stage(cur ^ 1, kc + 1); CP_WAIT(1); }
        else              { CP_WAIT(0); }
        __syncthreads();

        unsigned* As = sm + cur * STAGE;
        unsigned* Bs = As + 128 * SMS;

        #pragma unroll
        for (int ks = 0; ks < 2; ks++) {
            int kb8 = ks * 8;
            unsigned a[2][4];
            #pragma unroll
            for (int mt = 0; mt < 2; mt++) {
                int mr = wm * 32 + mt * 16 + g;
                a[mt][0] = As[mr * SMS + kb8 + t];
                a[mt][1] = As[(mr + 8) * SMS + kb8 + t];
                a[mt][2] = As[mr * SMS + kb8 + t + 4];
                a[mt][3] = As[(mr + 8) * SMS + kb8 + t + 4];
            }
            #pragma unroll
            for (int nt = 0; nt < 8; nt++) {
                int nr = wn * 64 + nt * 8 + g;
                unsigned b[2];
                b[0] = Bs[nr * SMS + kb8 + t];
                b[1] = Bs[nr * SMS + kb8 + t + 4];
                #pragma unroll
                for (int mt = 0; mt < 2; mt++) mma_bf16(acc[mt][nt], a[mt], b);
            }
        }
        __syncthreads();
    }

    if (ep_out == nullptr) {
        #pragma unroll
        for (int mt = 0; mt < 2; mt++) {
            int r0 = rowbase + wm * 32 + mt * 16 + g;
            int r1 = r0 + 8;
            float s0v = (r0 < NNODES) ? __ldg(&rden[r0]) : 0.f;
            float s1v = (r1 < NNODES) ? __ldg(&rden[r1]) : 0.f;
            #pragma unroll
            for (int nt = 0; nt < 8; nt++) {
                int col = wn * 64 + nt * 8 + t * 2;
                if (r0 < NNODES)
                    *(float2*)(hid_out + (size_t)r0 * HDIM + col) =
                        make_float2(acc[mt][nt][0] * s0v, acc[mt][nt][1] * s0v);
                if (r1 < NNODES)
                    *(float2*)(hid_out + (size_t)r1 * HDIM + col) =
                        make_float2(acc[mt][nt][2] * s1v, acc[mt][nt][3] * s1v);
            }
        }
        return;
    }

    // fused logits: stage scaled C tile into smem (pipeline area is dead)
    float* ct = (float*)sm;
    #pragma unroll
    for (int mt = 0; mt < 2; mt++) {
        int r0l = wm * 32 + mt * 16 + g;
        int r1l = r0l + 8;
        int gr0 = rowbase + r0l, gr1 = rowbase + r1l;
        float s0v = (gr0 < NNODES) ? __ldg(&rden[gr0]) : 0.f;
        float s1v = (gr1 < NNODES) ? __ldg(&rden[gr1]) : 0.f;
        #pragma unroll
        for (int nt = 0; nt < 8; nt++) {
            int col = wn * 64 + nt * 8 + t * 2;
            ct[r0l * CTS + col]     = acc[mt][nt][0] * s0v;
            ct[r0l * CTS + col + 1] = acc[mt][nt][1] * s0v;
            ct[r1l * CTS + col]     = acc[mt][nt][2] * s1v;
            ct[r1l * CTS + col + 1] = acc[mt][nt][3] * s1v;
        }
    }
    __syncthreads();

    if (tid < 128) {
        int row = tid;
        int gr = rowbase + row;
        if (gr < NNODES) {
            const float* hr  = ct + row * CTS;
            const float* psn = (const float*)sm + PS_OFF;
            float ss = 0.f;
            float d[PDIM];
            #pragma unroll
            for (int p = 0; p < PDIM; p++) d[p] = 0.f;
            #pragma unroll 4
            for (int i = 0; i < HDIM; i++) {
                float hv = hr[i];
                ss += hv * hv;
                #pragma unroll
                for (int p = 0; p < PDIM; p++) d[p] += hv * psn[p * HDIM + i];
            }
            float inv = 1.f / fmaxf(sqrtf(ss), 1e-12f);
            float mx = -1e30f;
            #pragma unroll
            for (int p = 0; p < PDIM; p++) { d[p] *= inv; mx = fmaxf(mx, d[p]); }
            float sum = 0.f;
            #pragma unroll
            for (int p = 0; p < PDIM; p++) { d[p] = expf(d[p] - mx); sum += d[p]; }
            float rs = 1.f / sum;
            float ent = 0.f;
            #pragma unroll
            for (int p = 0; p < PDIM; p++) { d[p] *= rs; ent -= d[p] * logf(d[p] + 1e-8f); }
            float exl = expf(-ent);
            float vals[32];
            #pragma unroll
            for (int p = 0; p < PDIM; p++) vals[p] = d[p] * exl;
            #pragma unroll
            for (int p = PDIM; p < 31; p++) vals[p] = 0.f;
            vals[31] = exl;
            float4* dp4 = (float4*)(ep_out + (size_t)gr * PSTRIDE);
            #pragma unroll
            for (int q = 0; q < 8; q++)
                dp4[q] = make_float4(vals[q * 4], vals[q * 4 + 1],
                                     vals[q * 4 + 2], vals[q * 4 + 3]);
        }
    }
}

// ---------------- classifier ----------------
__global__ void __launch_bounds__(128) k_classifier(
    const float* __restrict__ hidden, const int* __restrict__ tails,
    const float* __restrict__ proto, float* __restrict__ out, int B)
{
    __shared__ float ps[PDIM * HDIM];
    proto_to_smem(proto, ps);
    int t = blockIdx.x * blockDim.x + threadIdx.x;
    if (t >= B) return;
    const float4* hp = (const float4*)(hidden + (size_t)__ldg(&tails[t]) * HDIM);
    float d[PDIM];
    #pragma unroll
    for (int p = 0; p < PDIM; p++) d[p] = 0.f;
    float ss = 0.f;
    for (int i = 0; i < HDIM / 4; i++) {
        float4 h = __ldg(hp + i);
        ss += h.x * h.x + h.y * h.y + h.z * h.z + h.w * h.w;
        #pragma unroll
        for (int p = 0; p < PDIM; p++) {
            float4 q = *(const float4*)(ps + p * HDIM + i * 4);
            d[p] += h.x * q.x + h.y * q.y + h.z * q.z + h.w * q.w;
        }
    }
    float inv = 1.f / fmaxf(sqrtf(ss), 1e-12f);
    #pragma unroll
    for (int p = 0; p < PDIM; p++) out[(size_t)t * PDIM + p] = d[p] * inv;
}

// ---------------- host ----------------
static inline int grd(int n, int b) { return (n + b - 1) / b; }

extern "C" void kernel_launch(void* const* d_in, const int* in_sizes, int n_in,
                              void* d_out, int out_size)
{
    const int*   edge_index = (const int*)d_in[0];
    const int*   etype      = (const int*)d_in[1];
    const int*   tails      = (const int*)d_in[2];
    const float* multi      = (const float*)d_in[3];
    const float* proto      = (const float*)d_in[4];
    const float* semb       = (const float*)d_in[5];
    float* out = (float*)d_out;

    int E = in_sizes[0] / 2;
    int B = in_sizes[2];
    int L = in_sizes[3] / (RDIM * PDIM * HDIM);
    const int* src = edge_index;
    const int* dst = edge_index + E;

    float *hid, *rden, *eproba;
    __nv_bfloat16 *A, *Bm;
    int *cnt, *run, *off, *srcs;
    cudaGetSymbolAddress((void**)&hid,    g_hidden);
    cudaGetSymbolAddress((void**)&eproba, g_eproba);
    cudaGetSymbolAddress((void**)&rden,   g_rden);
    cudaGetSymbolAddress((void**)&A,      g_A);
    cudaGetSymbolAddress((void**)&Bm,     g_B);
    cudaGetSymbolAddress((void**)&cnt,    g_cnt);
    cudaGetSymbolAddress((void**)&run,    g_run);
    cudaGetSymbolAddress((void**)&off,    g_off);
    cudaGetSymbolAddress((void**)&srcs,   g_srcs);

    const int TB = 256;
    const int SM_PLAIN = 2 * 2 * 128 * SMS * 4;             // 40960
    const int SM_FUSED = (PS_OFF + PDIM * HDIM) * 4;        // 75264
    const int SM_SCAN  = NNODES * 4;                        // 200000
    cudaFuncSetAttribute(k_gemm, cudaFuncAttributeMaxDynamicSharedMemorySize, SM_FUSED);
    cudaFuncSetAttribute(k_scanall, cudaFuncAttributeMaxDynamicSharedMemorySize, SM_SCAN);

    // ---- preprocessing (cnt/run are zero from init / previous run) ----
    k_setup<<<grd(E, TB), TB>>>(dst, cnt, E, A, multi, Bm, L * 128 * KUF);
    k_scanall<<<1, 1024, SM_SCAN>>>(cnt, run, off, proto, semb, eproba, E);
    k_rank<<<grd(E, TB), TB>>>(dst, etype, src, off, run, srcs, E);

    for (int l = 0; l < L; l++) {
        bool last = (l == L - 1);
        if (l == 0)
            k_build_W0<<<grd(NNODES * 32, TB), TB>>>(srcs, off, eproba, A, rden);
        else
            k_build_W<<<grd(NNODES * 32, TB), TB>>>(srcs, off, eproba, A, rden);
        k_gemm<<<NTILES, 256, last ? SM_PLAIN : SM_FUSED>>>(
            A, Bm + (size_t)l * 128 * KUF, rden,
            last ? nullptr : proto + (size_t)(l + 1) * PDIM * HDIM,
            last ? nullptr : eproba,
            last ? hid : nullptr);
    }

    k_classifier<<<grd(B, 128), 128>>>(
        hid, tails, proto + (size_t)(L - 1) * PDIM * HDIM, out, B);
}

// round 17
// speedup vs baseline: 1.3140x; 1.0517x over previous
#include <cuda_runtime.h>
#include <cuda_bf16.h>
#include <cstdint>

#define HDIM 128
#define PDIM 18
#define RDIM 18
#define NNODES 50000
#define NTILES 391
#define NROWS (NTILES * 128)     // 50048
#define MAXE 800000
#define PSTRIDE 32               // eproba row stride (f32); exl at col 19
#define KUF 352                  // K padded (bf16 elems per row)
#define KU32 176                 // u32 (bf16x2) per row
#define NCH 11                   // k chunks of 32 bf16 (16 u32)
#define SMS 20                   // pipeline smem row stride in u32
#define CTS 129                  // epilogue C-tile stride (f32)
#define PS_OFF 16512             // f32 offset of protos in gemm smem (128*129)
#define NSLAB 163                // per-node slab stride in float2
#define LMAX 3

// ---------------- scratch (device globals; no allocations allowed) ----------------
__device__ float         g_hidden[NNODES * HDIM];     // last-layer output only
__device__ float         g_eproba[NNODES * PSTRIDE];  // [n][p]=exl*proba, [n][19]=exl
__device__ float         g_rden[NNODES];
__device__ __nv_bfloat16 g_A[(size_t)NROWS * KUF];
__device__ __nv_bfloat16 g_B[LMAX * 128 * KUF];
__device__ int           g_cnt[NNODES];               // zero at init; re-zeroed by scanall
__device__ int           g_run[NNODES];               // zero at init; re-zeroed by scanall
__device__ int           g_off[NNODES + 1];
__device__ int           g_srcs[MAXE];                // packed (r<<26)|(src<<5), sorted by dst

// ---------------- helpers ----------------
__device__ __forceinline__ void cp_async16(void* sdst, const void* gsrc) {
    unsigned s = (unsigned)__cvta_generic_to_shared(sdst);
    asm volatile("cp.async.cg.shared.global [%0], [%1], 16;\n" :: "r"(s), "l"(gsrc));
}
#define CP_COMMIT() asm volatile("cp.async.commit_group;\n" ::: "memory")
#define CP_WAIT(n)  asm volatile("cp.async.wait_group %0;\n" :: "n"(n) : "memory")

__device__ __forceinline__ void mma_bf16(float* c, const unsigned* a, const unsigned* b) {
    asm volatile(
        "mma.sync.aligned.m16n8k16.row.col.f32.bf16.bf16.f32 "
        "{%0,%1,%2,%3}, {%4,%5,%6,%7}, {%8,%9}, {%0,%1,%2,%3};\n"
        : "+f"(c[0]), "+f"(c[1]), "+f"(c[2]), "+f"(c[3])
        : "r"(a[0]), "r"(a[1]), "r"(a[2]), "r"(a[3]), "r"(b[0]), "r"(b[1]));
}

// normalize PDIM proto rows into smem ps[]
__device__ __forceinline__ void proto_to_smem(const float* __restrict__ proto, float* ps) {
    int warp = threadIdx.x >> 5, lane = threadIdx.x & 31;
    int nw = blockDim.x >> 5;
    for (int p = warp; p < PDIM; p += nw) {
        float4 v = ((const float4*)(proto + p * HDIM))[lane];
        float ss = v.x * v.x + v.y * v.y + v.z * v.z + v.w * v.w;
        #pragma unroll
        for (int o = 16; o; o >>= 1) ss += __shfl_xor_sync(0xffffffffu, ss, o);
        float inv = 1.f / fmaxf(sqrtf(ss), 1e-12f);
        ((float4*)(ps + p * HDIM))[lane] = make_float4(v.x * inv, v.y * inv, v.z * inv, v.w * inv);
    }
    __syncthreads();
}

// warp-cooperative slab->A writeback for one node (slab = float2[r*9+s], cols 2s,2s+1)
__device__ __forceinline__ void writeback_node(
    const float2* Wg, __nv_bfloat16* A, size_t rowoff, int lane)
{
    uint32_t* Arow = (uint32_t*)(A + rowoff);
    #pragma unroll
    for (int rep = 0; rep < 6; rep++) {
        int i = rep * 32 + lane;
        if (i < 162) {
            unsigned r0 = (unsigned)i / 9u;
            int s0 = i - (int)r0 * 9;
            float2 v = Wg[r0 * 9 + s0];
            __nv_bfloat162 tt = __floats2bfloat162_rn(v.x, v.y);
            Arow[i] = *(uint32_t*)&tt;
        }
    }
    if (lane < KU32 - 162) Arow[162 + lane] = 0;   // pad cols 324..351
}

// ---------------- setup (cnt assumed zero): hist + A pad + B build ----------------
__global__ void k_setup(const int* __restrict__ dst, int* __restrict__ cnt, int E,
                        __nv_bfloat16* __restrict__ A,
                        const float* __restrict__ M, __nv_bfloat16* __restrict__ B,
                        int btotal) {
    int i = blockIdx.x * blockDim.x + threadIdx.x;
    if (i < E) atomicAdd(&cnt[dst[i]], 1);
    if (i < (NROWS - NNODES) * KUF)
        A[(size_t)NNODES * KUF + i] = __float2bfloat16(0.f);
    if (i < btotal) {                          // B[l][h][k] = bf16(M[l][k/18][k%18][h])
        int l = i / (128 * KUF);
        int rem = i - l * 128 * KUF;
        int h = rem / KUF, k = rem % KUF;
        float v = 0.f;
        if (k < RDIM * PDIM)
            v = __ldg(&M[(size_t)((l * RDIM + k / PDIM) * PDIM + k % PDIM) * HDIM + h]);
        B[i] = __float2bfloat16(v);
    }
}

// ---------------- smem-staged single-pass scan + re-zero cnt/run + node-0 eproba ----------------
__global__ void __launch_bounds__(1024) k_scanall(
    int* __restrict__ cnt, int* __restrict__ run, int* __restrict__ off,
    const float* __restrict__ proto0, const float* __restrict__ semb,
    float* __restrict__ eproba, int E)
{
    extern __shared__ int sc[];                // NNODES ints (200 KB)
    __shared__ int wsum[32];
    const int PER = (NNODES + 1023) / 1024;    // 49
    int tid = threadIdx.x, lane = tid & 31, wid = tid >> 5;

    #pragma unroll
    for (int r = 0; r < PER; r++) {
        int i = r * 1024 + tid;
        if (i < NNODES) sc[i] = cnt[i];
    }
    __syncthreads();

    int base = tid * PER;
    int lsum = 0;
    #pragma unroll 7
    for (int k = 0; k < PER; k++) {
        int i = base + k;
        if (i < NNODES) lsum += sc[i];
    }
    int x = lsum;
    #pragma unroll
    for (int o = 1; o < 32; o <<= 1) {
        int y = __shfl_up_sync(0xffffffffu, x, o);
        if (lane >= o) x += y;
    }
    if (lane == 31) wsum[wid] = x;
    __syncthreads();
    if (wid == 0) {
        int wv = wsum[lane];
        #pragma unroll
        for (int o = 1; o < 32; o <<= 1) {
            int y = __shfl_up_sync(0xffffffffu, wv, o);
            if (lane >= o) wv += y;
        }
        wsum[lane] = wv;
    }
    __syncthreads();
    int pfx = ((wid > 0) ? wsum[wid - 1] : 0) + x - lsum;
    #pragma unroll 7
    for (int k = 0; k < PER; k++) {
        int i = base + k;
        if (i < NNODES) { int v = sc[i]; sc[i] = pfx; pfx += v; }
    }
    __syncthreads();
    #pragma unroll
    for (int r = 0; r < PER; r++) {
        int i = r * 1024 + tid;
        if (i < NNODES) { off[i] = sc[i]; cnt[i] = 0; run[i] = 0; }
    }
    if (tid == 0) off[NNODES] = E;

    // node 0: real eproba row from semb vs layer-0 protos (warp 0); exl at col 19
    if (wid == 0) {
        float4 h = ((const float4*)semb)[lane];
        float ss = h.x * h.x + h.y * h.y + h.z * h.z + h.w * h.w;
        #pragma unroll
        for (int o = 16; o; o >>= 1) ss += __shfl_xor_sync(0xffffffffu, ss, o);
        float inv = 1.f / fmaxf(sqrtf(ss), 1e-12f);
        float d[PDIM];
        #pragma unroll
        for (int p = 0; p < PDIM; p++) {
            float4 q = ((const float4*)(proto0 + p * HDIM))[lane];
            float sp = q.x * q.x + q.y * q.y + q.z * q.z + q.w * q.w;
            float dp = h.x * q.x + h.y * q.y + h.z * q.z + h.w * q.w;
            #pragma unroll
            for (int o = 16; o; o >>= 1) {
                sp += __shfl_xor_sync(0xffffffffu, sp, o);
                dp += __shfl_xor_sync(0xffffffffu, dp, o);
            }
            d[p] = dp * inv / fmaxf(sqrtf(sp), 1e-12f);
        }
        float mx = -1e30f;
        #pragma unroll
        for (int p = 0; p < PDIM; p++) mx = fmaxf(mx, d[p]);
        float sum = 0.f;
        #pragma unroll
        for (int p = 0; p < PDIM; p++) { d[p] = expf(d[p] - mx); sum += d[p]; }
        float rs = 1.f / sum;
        float ent = 0.f;
        #pragma unroll
        for (int p = 0; p < PDIM; p++) { d[p] *= rs; ent -= d[p] * logf(d[p] + 1e-8f); }
        float exl = expf(-ent);
        if (lane == 0) {
            #pragma unroll
            for (int p = 0; p < PDIM; p++) eproba[p] = d[p] * exl;
            eproba[18] = 0.f;
            eproba[19] = exl;
            #pragma unroll
            for (int p = 20; p < 32; p++) eproba[p] = 0.f;
        }
    }
}

// ---------------- rank: pack (r<<26) | (src<<5) ----------------
__global__ void k_rank(const int* __restrict__ dst, const int* __restrict__ et,
                       const int* __restrict__ src,
                       const int* __restrict__ off, int* __restrict__ run,
                       int* __restrict__ srcs, int E) {
    int e = blockIdx.x * blockDim.x + threadIdx.x;
    if (e >= E) return;
    int d = dst[e];
    int pos = off[d] + atomicAdd(&run[d], 1);
    srcs[pos] = (et[e] << 26) | (src[e] << 5);
}

// ---------------- build W general: 3 nodes per warp, float2 groups of 10 lanes ----------------
__global__ void __launch_bounds__(256) k_build_W(
    const int* __restrict__ srcs, const int* __restrict__ off,
    const float* __restrict__ eproba,
    __nv_bfloat16* __restrict__ A, float* __restrict__ rden)
{
    __shared__ float2 sW[8][3 * NSLAB];
    int wglob = (blockIdx.x * blockDim.x + threadIdx.x) >> 5;
    int wl = (threadIdx.x >> 5);
    int lane = threadIdx.x & 31;
    int grp = lane / 10;                    // 0,1,2 (lanes 30,31 -> 3: inactive)
    int sub = lane - grp * 10;
    int node = wglob * 3 + grp;
    bool active = (grp < 3) && (node < NNODES);
    float2* W2 = &sW[wl][(grp < 3 ? grp : 0) * NSLAB];

    for (int i = lane; i < 3 * NSLAB; i += 32) sW[wl][i] = make_float2(0.f, 0.f);
    __syncwarp();

    int beg = active ? __ldg(&off[node]) : 0;
    int end = active ? __ldg(&off[node + 1]) : 0;
    int len = end - beg;
    int ml = len;
    #pragma unroll
    for (int o = 16; o; o >>= 1) ml = max(ml, __shfl_xor_sync(0xffffffffu, ml, o));

    const float2* ep2 = (const float2*)eproba;
    float den = 0.f;
    int s = 0;
    for (; s + 1 < ml; s += 2) {
        bool p0 = s < len, p1 = s + 1 < len;
        unsigned pka = p0 ? (unsigned)__ldg(&srcs[beg + s]) : 0u;
        unsigned pkb = p1 ? (unsigned)__ldg(&srcs[beg + s + 1]) : 0u;
        float2 ea = p0 ? __ldg(&ep2[((pka & 0x03FFFFFFu) >> 1) + sub]) : make_float2(0.f, 0.f);
        float2 eb = p1 ? __ldg(&ep2[((pkb & 0x03FFFFFFu) >> 1) + sub]) : make_float2(0.f, 0.f);
        if (sub < 9) {
            if (p0) {
                float2 w = W2[(pka >> 26) * 9 + sub];
                w.x += ea.x; w.y += ea.y;
                W2[(pka >> 26) * 9 + sub] = w;
            }
            if (p1) {
                float2 w = W2[(pkb >> 26) * 9 + sub];
                w.x += eb.x; w.y += eb.y;
                W2[(pkb >> 26) * 9 + sub] = w;
            }
        } else {
            den += ea.y + eb.y;             // col 19 = exl
        }
    }
    if (s < ml) {
        bool p0 = s < len;
        unsigned pka = p0 ? (unsigned)__ldg(&srcs[beg + s]) : 0u;
        float2 ea = p0 ? __ldg(&ep2[((pka & 0x03FFFFFFu) >> 1) + sub]) : make_float2(0.f, 0.f);
        if (sub < 9) {
            if (p0) {
                float2 w = W2[(pka >> 26) * 9 + sub];
                w.x += ea.x; w.y += ea.y;
                W2[(pka >> 26) * 9 + sub] = w;
            }
        } else {
            den += ea.y;
        }
    }
    if (active && sub == 9) rden[node] = (len == 0) ? 0.f : (1.f / den);
    __syncwarp();

    #pragma unroll 1
    for (int g2 = 0; g2 < 3; g2++) {
        int nd = wglob * 3 + g2;
        if (nd >= NNODES) break;
        writeback_node(&sW[wl][g2 * NSLAB], A, (size_t)nd * KUF, lane);
    }
}

// ---------------- build W layer 0: 3 nodes per warp, constant eproba ----------------
__global__ void __launch_bounds__(256) k_build_W0(
    const int* __restrict__ srcs, const int* __restrict__ off,
    const float* __restrict__ eproba,
    __nv_bfloat16* __restrict__ A, float* __restrict__ rden)
{
    __shared__ float2 sW[8][3 * NSLAB];
    int wglob = (blockIdx.x * blockDim.x + threadIdx.x) >> 5;
    int wl = (threadIdx.x >> 5);
    int lane = threadIdx.x & 31;
    int grp = lane / 10;
    int sub = lane - grp * 10;
    int node = wglob * 3 + grp;
    bool active = (grp < 3) && (node < NNODES);
    float2* W2 = &sW[wl][(grp < 3 ? grp : 0) * NSLAB];

    for (int i = lane; i < 3 * NSLAB; i += 32) sW[wl][i] = make_float2(0.f, 0.f);
    __syncwarp();

    int beg = active ? __ldg(&off[node]) : 0;
    int end = active ? __ldg(&off[node + 1]) : 0;
    int len = end - beg;
    int ml = len;
    #pragma unroll
    for (int o = 16; o; o >>= 1) ml = max(ml, __shfl_xor_sync(0xffffffffu, ml, o));

    const float2* ep2 = (const float2*)eproba;
    const float pu = 1.f / 18.f;
    const float exlu = pu + 1e-8f;
    const float2 ebase = (sub < 9) ? make_float2(pu * exlu, pu * exlu)
                                   : make_float2(0.f, exlu);
    const float2 sp = __ldg(&ep2[sub]);     // node-0 row

    float den = 0.f;
    for (int s = 0; s < ml; s++) {
        bool p0 = s < len;
        unsigned pka = p0 ? (unsigned)__ldg(&srcs[beg + s]) : 0x20u;  // src=1 sentinel
        float2 e = ((pka & 0x03FFFFFFu) == 0u) ? sp : ebase;
        if (sub < 9) {
            if (p0) {
                float2 w = W2[(pka >> 26) * 9 + sub];
                w.x += e.x; w.y += e.y;
                W2[(pka >> 26) * 9 + sub] = w;
            }
        } else if (p0) {
            den += e.y;
        }
    }
    if (active && sub == 9) rden[node] = (len == 0) ? 0.f : (1.f / den);
    __syncwarp();

    #pragma unroll 1
    for (int g2 = 0; g2 < 3; g2++) {
        int nd = wglob * 3 + g2;
        if (nd >= NNODES) break;
        writeback_node(&sW[wl][g2 * NSLAB], A, (size_t)nd * KUF, lane);
    }
}

// ---------------- bf16 GEMM + fused next-layer logits epilogue ----------------
__global__ void __launch_bounds__(256) k_gemm(
    const __nv_bfloat16* __restrict__ A_, const __nv_bfloat16* __restrict__ B_,
    const float* __restrict__ rden,
    const float* __restrict__ proto_next,
    float* __restrict__ ep_out,
    float* __restrict__ hid_out)
{
    extern __shared__ unsigned sm[];
    int tid = threadIdx.x;
    int wid = tid >> 5, lane = tid & 31;
    int wm = wid & 3, wn = wid >> 2;
    int g = lane >> 2, t = lane & 3;
    int rowbase = blockIdx.x * 128;

    if (ep_out) proto_to_smem(proto_next, (float*)sm + PS_OFF);

    const unsigned* Ag = (const unsigned*)A_;
    const unsigned* Bg = (const unsigned*)B_;

    float acc[2][8][4];
    #pragma unroll
    for (int mt = 0; mt < 2; mt++)
        #pragma unroll
        for (int nt = 0; nt < 8; nt++)
            #pragma unroll
            for (int c = 0; c < 4; c++) acc[mt][nt][c] = 0.f;

    const int STAGE = 2 * 128 * SMS;

    auto load_stage = [&](int stage, int kc) {
        unsigned* sb = sm + stage * STAGE;
        int kb = kc * 16;
        #pragma unroll
        for (int i = 0; i < 2; i++) {
            int q = i * 256 + tid;
            int row = q >> 2;
            int c4 = (q & 3) * 4;
            cp_async16(sb + row * SMS + c4, Ag + (size_t)(rowbase + row) * KU32 + kb + c4);
            cp_async16(sb + 128 * SMS + row * SMS + c4, Bg + (size_t)row * KU32 + kb + c4);
        }
        CP_COMMIT();
    };

    load_stage(0, 0);

    #pragma unroll 1
    for (int kc = 0; kc < NCH; kc++) {
        int cur = kc & 1;
        if (kc + 1 < NCH) { load_stage(cur ^ 1, kc + 1); CP_WAIT(1); }
        else              { CP_WAIT(0); }
        __syncthreads();

        unsigned* As = sm + cur * STAGE;
        unsigned* Bs = As + 128 * SMS;

        #pragma unroll
        for (int ks = 0; ks < 2; ks++) {
            int kb8 = ks * 8;
            unsigned a[2][4];
            #pragma unroll
            for (int mt = 0; mt < 2; mt++) {
                int mr = wm * 32 + mt * 16 + g;
                a[mt][0] = As[mr * SMS + kb8 + t];
                a[mt][1] = As[(mr + 8) * SMS + kb8 + t];
                a[mt][2] = As[mr * SMS + kb8 + t + 4];
                a[mt][3] = As[(mr + 8) * SMS + kb8 + t + 4];
            }
            #pragma unroll
            for (int nt = 0; nt < 8; nt++) {
                int nr = wn * 64 + nt * 8 + g;
                unsigned b[2];
                b[0] = Bs[nr * SMS + kb8 + t];
                b[1] = Bs[nr * SMS + kb8 + t + 4];
                #pragma unroll
                for (int mt = 0; mt < 2; mt++) mma_bf16(acc[mt][nt], a[mt], b);
            }
        }
        __syncthreads();
    }

    if (ep_out == nullptr) {
        #pragma unroll
        for (int mt = 0; mt < 2; mt++) {
            int r0 = rowbase + wm * 32 + mt * 16 + g;
            int r1 = r0 + 8;
            float s0v = (r0 < NNODES) ? __ldg(&rden[r0]) : 0.f;
            float s1v = (r1 < NNODES) ? __ldg(&rden[r1]) : 0.f;
            #pragma unroll
            for (int nt = 0; nt < 8; nt++) {
                int col = wn * 64 + nt * 8 + t * 2;
                if (r0 < NNODES)
                    *(float2*)(hid_out + (size_t)r0 * HDIM + col) =
                        make_float2(acc[mt][nt][0] * s0v, acc[mt][nt][1] * s0v);
                if (r1 < NNODES)
                    *(float2*)(hid_out + (size_t)r1 * HDIM + col) =
                        make_float2(acc[mt][nt][2] * s1v, acc[mt][nt][3] * s1v);
            }
        }
        return;
    }

    // fused logits: stage scaled C tile into smem (pipeline area is dead)
    float* ct = (float*)sm;
    #pragma unroll
    for (int mt = 0; mt < 2; mt++) {
        int r0l = wm * 32 + mt * 16 + g;
        int r1l = r0l + 8;
        int gr0 = rowbase + r0l, gr1 = rowbase + r1l;
        float s0v = (gr0 < NNODES) ? __ldg(&rden[gr0]) : 0.f;
        float s1v = (gr1 < NNODES) ? __ldg(&rden[gr1]) : 0.f;
        #pragma unroll
        for (int nt = 0; nt < 8; nt++) {
            int col = wn * 64 + nt * 8 + t * 2;
            ct[r0l * CTS + col]     = acc[mt][nt][0] * s0v;
            ct[r0l * CTS + col + 1] = acc[mt][nt][1] * s0v;
            ct[r1l * CTS + col]     = acc[mt][nt][2] * s1v;
            ct[r1l * CTS + col + 1] = acc[mt][nt][3] * s1v;
        }
    }
    __syncthreads();

    if (tid < 128) {
        int row = tid;
        int gr = rowbase + row;
        if (gr < NNODES) {
            const float* hr  = ct + row * CTS;
            const float* psn = (const float*)sm + PS_OFF;
            float ss = 0.f;
            float d[PDIM];
            #pragma unroll
            for (int p = 0; p < PDIM; p++) d[p] = 0.f;
            #pragma unroll 4
            for (int i = 0; i < HDIM; i++) {
                float hv = hr[i];
                ss += hv * hv;
                #pragma unroll
                for (int p = 0; p < PDIM; p++) d[p] += hv * psn[p * HDIM + i];
            }
            float inv = 1.f / fmaxf(sqrtf(ss), 1e-12f);
            float mx = -1e30f;
            #pragma unroll
            for (int p = 0; p < PDIM; p++) { d[p] *= inv; mx = fmaxf(mx, d[p]); }
            float sum = 0.f;
            #pragma unroll
            for (int p = 0; p < PDIM; p++) { d[p] = expf(d[p] - mx); sum += d[p]; }
            float rs = 1.f / sum;
            float ent = 0.f;
            #pragma unroll
            for (int p = 0; p < PDIM; p++) { d[p] *= rs; ent -= d[p] * logf(d[p] + 1e-8f); }
            float exl = expf(-ent);
            float vals[32];
            #pragma unroll
            for (int p = 0; p < PDIM; p++) vals[p] = d[p] * exl;
            vals[18] = 0.f;
            vals[19] = exl;                  // exl at col 19
            #pragma unroll
            for (int p = 20; p < 32; p++) vals[p] = 0.f;
            float4* dp4 = (float4*)(ep_out + (size_t)gr * PSTRIDE);
            #pragma unroll
            for (int q = 0; q < 8; q++)
                dp4[q] = make_float4(vals[q * 4], vals[q * 4 + 1],
                                     vals[q * 4 + 2], vals[q * 4 + 3]);
        }
    }
}

// ---------------- classifier ----------------
__global__ void __launch_bounds__(128) k_classifier(
    const float* __restrict__ hidden, const int* __restrict__ tails,
    const float* __restrict__ proto, float* __restrict__ out, int B)
{
    __shared__ float ps[PDIM * HDIM];
    proto_to_smem(proto, ps);
    int t = blockIdx.x * blockDim.x + threadIdx.x;
    if (t >= B) return;
    const float4* hp = (const float4*)(hidden + (size_t)__ldg(&tails[t]) * HDIM);
    float d[PDIM];
    #pragma unroll
    for (int p = 0; p < PDIM; p++) d[p] = 0.f;
    float ss = 0.f;
    for (int i = 0; i < HDIM / 4; i++) {
        float4 h = __ldg(hp + i);
        ss += h.x * h.x + h.y * h.y + h.z * h.z + h.w * h.w;
        #pragma unroll
        for (int p = 0; p < PDIM; p++) {
            float4 q = *(const float4*)(ps + p * HDIM + i * 4);
            d[p] += h.x * q.x + h.y * q.y + h.z * q.z + h.w * q.w;
        }
    }
    float inv = 1.f / fmaxf(sqrtf(ss), 1e-12f);
    #pragma unroll
    for (int p = 0; p < PDIM; p++) out[(size_t)t * PDIM + p] = d[p] * inv;
}

// ---------------- host ----------------
static inline int grd(int n, int b) { return (n + b - 1) / b; }

extern "C" void kernel_launch(void* const* d_in, const int* in_sizes, int n_in,
                              void* d_out, int out_size)
{
    const int*   edge_index = (const int*)d_in[0];
    const int*   etype      = (const int*)d_in[1];
    const int*   tails      = (const int*)d_in[2];
    const float* multi      = (const float*)d_in[3];
    const float* proto      = (const float*)d_in[4];
    const float* semb       = (const float*)d_in[5];
    float* out = (float*)d_out;

    int E = in_sizes[0] / 2;
    int B = in_sizes[2];
    int L = in_sizes[3] / (RDIM * PDIM * HDIM);
    const int* src = edge_index;
    const int* dst = edge_index + E;

    float *hid, *rden, *eproba;
    __nv_bfloat16 *A, *Bm;
    int *cnt, *run, *off, *srcs;
    cudaGetSymbolAddress((void**)&hid,    g_hidden);
    cudaGetSymbolAddress((void**)&eproba, g_eproba);
    cudaGetSymbolAddress((void**)&rden,   g_rden);
    cudaGetSymbolAddress((void**)&A,      g_A);
    cudaGetSymbolAddress((void**)&Bm,     g_B);
    cudaGetSymbolAddress((void**)&cnt,    g_cnt);
    cudaGetSymbolAddress((void**)&run,    g_run);
    cudaGetSymbolAddress((void**)&off,    g_off);
    cudaGetSymbolAddress((void**)&srcs,   g_srcs);

    const int TB = 256;
    const int SM_PLAIN = 2 * 2 * 128 * SMS * 4;             // 40960
    const int SM_FUSED = (PS_OFF + PDIM * HDIM) * 4;        // 75264
    const int SM_SCAN  = NNODES * 4;                        // 200000
    cudaFuncSetAttribute(k_gemm, cudaFuncAttributeMaxDynamicSharedMemorySize, SM_FUSED);
    cudaFuncSetAttribute(k_scanall, cudaFuncAttributeMaxDynamicSharedMemorySize, SM_SCAN);

    // ---- preprocessing (cnt/run are zero from init / previous run) ----
    k_setup<<<grd(E, TB), TB>>>(dst, cnt, E, A, multi, Bm, L * 128 * KUF);
    k_scanall<<<1, 1024, SM_SCAN>>>(cnt, run, off, proto, semb, eproba, E);
    k_rank<<<grd(E, TB), TB>>>(dst, etype, src, off, run, srcs, E);

    int nwarps3 = (NNODES + 2) / 3;                          // 16667
    int bw_blocks = grd(nwarps3 * 32, TB);

    for (int l = 0; l < L; l++) {
        bool last = (l == L - 1);
        if (l == 0)
            k_build_W0<<<bw_blocks, TB>>>(srcs, off, eproba, A, rden);
        else
            k_build_W<<<bw_blocks, TB>>>(srcs, off, eproba, A, rden);
        k_gemm<<<NTILES, 256, last ? SM_PLAIN : SM_FUSED>>>(
            A, Bm + (size_t)l * 128 * KUF, rden,
            last ? nullptr : proto + (size_t)(l + 1) * PDIM * HDIM,
            last ? nullptr : eproba,
            last ? hid : nullptr);
    }

    k_classifier<<<grd(B, 128), 128>>>(
        hid, tails, proto + (size_t)(L - 1) * PDIM * HDIM, out, B);
}